// round 12
// baseline (speedup 1.0000x reference)
#include <cuda_runtime.h>
#include <cuda_fp16.h>
#include <cstdint>

#define BATCH 8192
#define SEQ   40
#define HID   256
#define VOCAB 128

// ===========================================================================
// Global scratch (no cudaMalloc allowed)
// ===========================================================================
// A fragments (h state, single fp16 plane), ping-pong.
// block = grp*16 + kc*2 + ks; grp = batch/16. 32 lanes x uint4.
__device__ __align__(16) uint4 g_Afrag[2][8192][32];
// B fragments (Wh fp16). block = (jt*4+jw)*32 + it*2 + gp.
__device__ __align__(16) uint4 g_Bfrag[1024][32];
__device__ float g_c[BATCH * HID];
__device__ float g_Wxb[128 * 1024];
__device__ float g_hfin[BATCH * HID];
__device__ int   g_inT[SEQ * BATCH];

__device__ __forceinline__ uint32_t smem_to_u32(const void* p) {
    uint32_t a;
    asm("{ .reg .u64 tmp; cvta.to.shared.u64 tmp, %1; cvt.u32.u64 %0, tmp; }"
        : "=r"(a) : "l"(p));
    return a;
}

#define CP_ASYNC16(dst, src) \
    asm volatile("cp.async.cg.shared.global [%0], [%1], 16;" \
        :: "r"(dst), "l"(src) : "memory")
#define CP_COMMIT() asm volatile("cp.async.commit_group;" ::: "memory")
#define CP_WAIT1()  asm volatile("cp.async.wait_group 1;" ::: "memory")
#define CP_WAIT0()  asm volatile("cp.async.wait_group 0;" ::: "memory")

#define LDS128(r0, r1, r2, r3, addr) \
    asm volatile("ld.shared.v4.b32 {%0,%1,%2,%3}, [%4];" \
        : "=r"(r0), "=r"(r1), "=r"(r2), "=r"(r3) : "r"(addr))

#define MMA16816(d, a, b0, b1) \
    asm volatile("mma.sync.aligned.m16n8k16.row.col.f32.f16.f16.f32 " \
        "{%0,%1,%2,%3}, {%4,%5,%6,%7}, {%8,%9}, {%0,%1,%2,%3};" \
        : "+f"((d)[0]), "+f"((d)[1]), "+f"((d)[2]), "+f"((d)[3]) \
        : "r"((a)[0]), "r"((a)[1]), "r"((a)[2]), "r"((a)[3]), \
          "r"(b0), "r"(b1))

__device__ __forceinline__ float sigf(float x) {
    return 1.0f / (1.0f + __expf(-x));
}
__device__ __forceinline__ float tanh_(float x) {
    float ax = fabsf(x);
    float e  = __expf(-2.0f * ax);
    float r  = (1.0f - e) / (1.0f + e);
    return copysignf(r, x);
}

// ===========================================================================
// Fused prep: init state + Wh->B frags + Wx+b + input transpose (1 launch)
// grid 2048 x 256 = 524288 threads
// ===========================================================================
__global__ void prep_all_kernel(const int*   __restrict__ inputs,
                                const float* __restrict__ Wh,
                                const float* __restrict__ Wx,
                                const float* __restrict__ bias) {
    int i = blockIdx.x * blockDim.x + threadIdx.x;

    // init c (all 524288 float4)
    ((float4*)g_c)[i] = make_float4(0.f, 0.f, 0.f, 0.f);

    // init A-frag buffer 0
    if (i < 262144)
        ((uint4*)g_Afrag[0])[i] = make_uint4(0, 0, 0, 0);

    // Wh -> B fragments (fp16)
    if (i < 262144) {
        int k = i >> 10, col = i & 1023;
        __half hi = __float2half(Wh[i]);
        int gate = col >> 8, j = col & 255;
        int jt = j >> 5, jw = (j >> 3) & 3, nl = j & 7;
        int kc = k >> 5, ks = (k >> 4) & 1, kk = k & 15;
        int gp = gate >> 1, gs = gate & 1;
        int lane = nl * 4 + ((kk & 7) >> 1);
        int reg  = kk >> 3;
        int hp   = kk & 1;
        int block = (jt * 4 + jw) * 32 + (kc * 2 + ks) * 2 + gp;
        ((__half*)g_Bfrag)[((size_t)block * 32 + lane) * 8 + gs * 4 + reg * 2 + hp] = hi;
    }

    // Wx + bias
    if (i < 131072)
        g_Wxb[i] = Wx[i] + bias[i & 1023];

    // transpose chars
    if (i < SEQ * BATCH) {
        int b = i / SEQ, tt = i - b * SEQ;
        g_inT[tt * BATCH + b] = inputs[i];
    }
}

// ===========================================================================
// LSTM step. CTA: 2 bx tiles (same jt), 256 thr = 8 warps (2 mw x 4 jw);
// warp tile M=32 x (4g x 8j) per tile. A double-buffered in SMEM (2x32KB),
// both tiles' cp.async issued up-front. Inner loop identical to r10.
// ===========================================================================
#define SMEM_TOTAL 65536

__global__ __launch_bounds__(256, 3) void lstm_step_kernel(int t) {
    extern __shared__ __align__(16) unsigned char smem[];
    const uint32_t sA = smem_to_u32(smem);
    const int tid  = threadIdx.x;
    const int lane = tid & 31, wid = tid >> 5;
    const int mw = wid >> 2;          // 0..1
    const int jw = wid & 3;           // 0..3
    const int bxg = blockIdx.x;       // 0..63  (tiles bx = bxg*2, bxg*2+1)
    const int jt  = blockIdx.y;       // 0..7

    // ---- issue cp.async for BOTH A tiles (2048 uint4 each)
#pragma unroll
    for (int q = 0; q < 2; q++) {
        const uint4* Asrc = &g_Afrag[t & 1][(bxg * 2 + q) * 64][0];
        const uint32_t dst = sA + q * 32768;
#pragma unroll
        for (int i = 0; i < 8; i++)
            CP_ASYNC16(dst + tid * 16 + i * 4096,
                       (const char*)(Asrc + i * 256 + tid));
        CP_COMMIT();
    }

    const int gq = lane >> 2, t4 = lane & 3;
    const int jcol = jt * 32 + jw * 8 + t4 * 2;
    const int blk_base = jt * 2 + (jw >> 1);
    const uint4* __restrict__ Bp = &g_Bfrag[(jt * 4 + jw) * 32][lane];
    uint32_t* __restrict__ Aout = (uint32_t*)g_Afrag[(t + 1) & 1];

    CP_WAIT1();        // tile 0 ready (tile 1 may still stream)
    __syncthreads();

#pragma unroll 1
    for (int q = 0; q < 2; q++) {
        const int bx = bxg * 2 + q;
        const uint32_t base = sA + q * 32768;

        // chars for this tile
        int ch[2][2];
#pragma unroll
        for (int mt = 0; mt < 2; mt++)
#pragma unroll
            for (int rr = 0; rr < 2; rr++)
                ch[mt][rr] = g_inT[t * BATCH + bx * 64 + mw * 32
                                   + mt * 16 + gq + rr * 8];

        uint4 bv0 = Bp[0], bv1 = Bp[32];

        float acc[2][4][4];
#pragma unroll
        for (int mt = 0; mt < 2; mt++)
#pragma unroll
            for (int g = 0; g < 4; g++)
#pragma unroll
                for (int e = 0; e < 4; e++) acc[mt][g][e] = 0.0f;

        const uint32_t aoff0 = base + (mw * 2 + 0) * 8192 + lane * 16;
        const uint32_t aoff1 = base + (mw * 2 + 1) * 8192 + lane * 16;

#pragma unroll 4
        for (int it = 0; it < 16; it++) {
            uint4 bn0, bn1;
            if (it < 15) {
                const uint4* p = Bp + (it + 1) * 64;
                bn0 = p[0]; bn1 = p[32];
            } else {
                bn0 = bv0; bn1 = bv1;
            }

            uint32_t ah[2][4];
            {
                uint32_t o = it * 512;
                LDS128(ah[0][0], ah[0][1], ah[0][2], ah[0][3], aoff0 + o);
                LDS128(ah[1][0], ah[1][1], ah[1][2], ah[1][3], aoff1 + o);
            }

#pragma unroll
            for (int mt = 0; mt < 2; mt++) {
                MMA16816(acc[mt][0], ah[mt], bv0.x, bv0.y);
                MMA16816(acc[mt][1], ah[mt], bv0.z, bv0.w);
                MMA16816(acc[mt][2], ah[mt], bv1.x, bv1.y);
                MMA16816(acc[mt][3], ah[mt], bv1.z, bv1.w);
            }
            bv0 = bn0; bv1 = bn1;
        }

        // ---- epilogue for this tile
#pragma unroll
        for (int mt = 0; mt < 2; mt++) {
            const int grp = bx * 4 + mw * 2 + mt;
#pragma unroll
            for (int rr = 0; rr < 2; rr++) {
                const int b = bx * 64 + mw * 32 + mt * 16 + gq + rr * 8;
                const float* wrow = g_Wxb + (size_t)ch[mt][rr] * 1024;
                float2 wx2[4];
#pragma unroll
                for (int g = 0; g < 4; g++)
                    wx2[g] = *(const float2*)&wrow[g * 256 + jcol];
                float2 c2 = *(const float2*)&g_c[(size_t)b * HID + jcol];

                float cn[2], hn[2];
#pragma unroll
                for (int e = 0; e < 2; e++) {
                    float zi = acc[mt][0][rr * 2 + e] + (e ? wx2[0].y : wx2[0].x);
                    float zf = acc[mt][1][rr * 2 + e] + (e ? wx2[1].y : wx2[1].x);
                    float zg = acc[mt][2][rr * 2 + e] + (e ? wx2[2].y : wx2[2].x);
                    float zo = acc[mt][3][rr * 2 + e] + (e ? wx2[3].y : wx2[3].x);
                    float ig = sigf(zi), fg = sigf(zf);
                    float gg = tanh_(zg), og = sigf(zo);
                    float cold = e ? c2.y : c2.x;
                    float cc = fg * cold + ig * gg;
                    cn[e] = cc;
                    hn[e] = og * tanh_(cc);
                }
                *(float2*)&g_c[(size_t)b * HID + jcol] = make_float2(cn[0], cn[1]);

                __half2 phi = __halves2half2(__float2half(hn[0]),
                                             __float2half(hn[1]));
                const int reg = rr + 2 * (jw & 1);
                uint32_t idx =
                    (uint32_t)(((grp * 16 + blk_base) * 32 + lane) * 4 + reg);
                Aout[idx] = *(uint32_t*)&phi;

                if (t == SEQ - 1)
                    *(float2*)&g_hfin[(size_t)b * HID + jcol] =
                        make_float2(hn[0], hn[1]);
            }
        }

        if (q == 0) {
            CP_WAIT0();        // own async parts of tile 1 done
            __syncthreads();   // everyone's parts visible
        }
    }
}

// ===========================================================================
// Dense + softmax (reads g_hfin, float)
// ===========================================================================
#define DROWS 8

__global__ __launch_bounds__(128) void dense_softmax_kernel(
    const float* __restrict__ Wd,   // [256, 128]
    const float* __restrict__ bd,   // [128]
    float*       __restrict__ out)  // [BATCH, 128]
{
    const int b0  = blockIdx.x * DROWS;
    const int tid = threadIdx.x;

    __shared__ float hs[DROWS][HID];
    __shared__ float ls[DROWS][VOCAB];

#pragma unroll
    for (int s = 0; s < DROWS * HID / 128; s++) {
        int e = tid + s * 128;
        hs[e >> 8][e & 255] = g_hfin[(size_t)b0 * HID + e];
    }
    __syncthreads();

    float acc[DROWS];
    float bv = bd[tid];
#pragma unroll
    for (int r = 0; r < DROWS; r++) acc[r] = bv;

#pragma unroll 8
    for (int k = 0; k < HID; k++) {
        float w = Wd[k * VOCAB + tid];
#pragma unroll
        for (int r = 0; r < DROWS; r++) acc[r] += hs[r][k] * w;
    }

#pragma unroll
    for (int r = 0; r < DROWS; r++) ls[r][tid] = acc[r];
    __syncthreads();

    const int w = tid >> 5, lane = tid & 31;
#pragma unroll
    for (int rr = 0; rr < 2; rr++) {
        int r = w * 2 + rr;
        float v[4];
        float m = -1e30f;
#pragma unroll
        for (int q = 0; q < 4; q++) {
            v[q] = ls[r][lane + q * 32];
            m = fmaxf(m, v[q]);
        }
#pragma unroll
        for (int o = 16; o > 0; o >>= 1) m = fmaxf(m, __shfl_xor_sync(0xffffffffu, m, o));
        float s = 0.0f;
#pragma unroll
        for (int q = 0; q < 4; q++) {
            v[q] = __expf(v[q] - m);
            s += v[q];
        }
#pragma unroll
        for (int o = 16; o > 0; o >>= 1) s += __shfl_xor_sync(0xffffffffu, s, o);
        float inv = 1.0f / s;
#pragma unroll
        for (int q = 0; q < 4; q++)
            out[(b0 + r) * VOCAB + lane + q * 32] = v[q] * inv;
    }
}

// ===========================================================================
extern "C" void kernel_launch(void* const* d_in, const int* in_sizes, int n_in,
                              void* d_out, int out_size) {
    const int*   inputs = (const int*)d_in[0];
    const float* Wx     = (const float*)d_in[1];
    const float* Wh     = (const float*)d_in[2];
    const float* b      = (const float*)d_in[3];
    const float* Wd     = (const float*)d_in[4];
    const float* bd     = (const float*)d_in[5];
    float*       out    = (float*)d_out;

    cudaFuncSetAttribute(lstm_step_kernel,
                         cudaFuncAttributeMaxDynamicSharedMemorySize, SMEM_TOTAL);

    prep_all_kernel<<<2048, 256>>>(inputs, Wh, Wx, b);

    dim3 grid(BATCH / 128, 8);  // 64 x 8 = 512 CTAs, 2 tiles each
    for (int t = 0; t < SEQ; t++)
        lstm_step_kernel<<<grid, 256, SMEM_TOTAL>>>(t);

    dense_softmax_kernel<<<BATCH / DROWS, 128>>>(Wd, bd, out);
}

// round 13
// speedup vs baseline: 1.2163x; 1.2163x over previous
#include <cuda_runtime.h>
#include <cuda_fp16.h>
#include <cstdint>

#define BATCH 8192
#define SEQ   40
#define HID   256
#define VOCAB 128

// ===========================================================================
// Global scratch (no cudaMalloc allowed)
// ===========================================================================
// A fragments (h state, single fp16 plane), ping-pong.
// block = grp*16 + kc*2 + ks; grp = batch/16. 32 lanes x uint4.
__device__ __align__(16) uint4 g_Afrag[2][8192][32];
// B fragments (Wh fp16). block = (jt*4+jw)*32 + it*2 + gp.
__device__ __align__(16) uint4 g_Bfrag[1024][32];
__device__ float g_c[BATCH * HID];
__device__ float g_Wxb[128 * 1024];
__device__ float g_hfin[BATCH * HID];
__device__ int   g_inT[SEQ * BATCH];

__device__ __forceinline__ uint32_t smem_to_u32(const void* p) {
    uint32_t a;
    asm("{ .reg .u64 tmp; cvta.to.shared.u64 tmp, %1; cvt.u32.u64 %0, tmp; }"
        : "=r"(a) : "l"(p));
    return a;
}

#define CP_ASYNC16(dst, src) \
    asm volatile("cp.async.cg.shared.global [%0], [%1], 16;" \
        :: "r"(dst), "l"(src) : "memory")
#define CP_COMMIT() asm volatile("cp.async.commit_group;" ::: "memory")
#define CP_WAIT0()  asm volatile("cp.async.wait_group 0;" ::: "memory")

#define LDS128(r0, r1, r2, r3, addr) \
    asm volatile("ld.shared.v4.b32 {%0,%1,%2,%3}, [%4];" \
        : "=r"(r0), "=r"(r1), "=r"(r2), "=r"(r3) : "r"(addr))

#define MMA16816(d, a, b0, b1) \
    asm volatile("mma.sync.aligned.m16n8k16.row.col.f32.f16.f16.f32 " \
        "{%0,%1,%2,%3}, {%4,%5,%6,%7}, {%8,%9}, {%0,%1,%2,%3};" \
        : "+f"((d)[0]), "+f"((d)[1]), "+f"((d)[2]), "+f"((d)[3]) \
        : "r"((a)[0]), "r"((a)[1]), "r"((a)[2]), "r"((a)[3]), \
          "r"(b0), "r"(b1))

__device__ __forceinline__ float sigf(float x) {
    return 1.0f / (1.0f + __expf(-x));
}
__device__ __forceinline__ float tanh_(float x) {
    float ax = fabsf(x);
    float e  = __expf(-2.0f * ax);
    float r  = (1.0f - e) / (1.0f + e);
    return copysignf(r, x);
}

// ===========================================================================
// Fused prep: init state + Wh->B frags + Wx+b + input transpose (1 launch)
// grid 2048 x 256 = 524288 threads
// ===========================================================================
__global__ void prep_all_kernel(const int*   __restrict__ inputs,
                                const float* __restrict__ Wh,
                                const float* __restrict__ Wx,
                                const float* __restrict__ bias) {
    int i = blockIdx.x * blockDim.x + threadIdx.x;

    // init c (524288 float4)
    ((float4*)g_c)[i] = make_float4(0.f, 0.f, 0.f, 0.f);

    // init A-frag buffer 0
    if (i < 262144)
        ((uint4*)g_Afrag[0])[i] = make_uint4(0, 0, 0, 0);

    // Wh -> B fragments (fp16)
    if (i < 262144) {
        int k = i >> 10, col = i & 1023;
        __half hi = __float2half(Wh[i]);
        int gate = col >> 8, j = col & 255;
        int jt = j >> 5, jw = (j >> 3) & 3, nl = j & 7;
        int kc = k >> 5, ks = (k >> 4) & 1, kk = k & 15;
        int gp = gate >> 1, gs = gate & 1;
        int lane = nl * 4 + ((kk & 7) >> 1);
        int reg  = kk >> 3;
        int hp   = kk & 1;
        int block = (jt * 4 + jw) * 32 + (kc * 2 + ks) * 2 + gp;
        ((__half*)g_Bfrag)[((size_t)block * 32 + lane) * 8 + gs * 4 + reg * 2 + hp] = hi;
    }

    // Wx + bias
    if (i < 131072)
        g_Wxb[i] = Wx[i] + bias[i & 1023];

    // transpose chars
    if (i < SEQ * BATCH) {
        int b = i / SEQ, tt = i - b * SEQ;
        g_inT[tt * BATCH + b] = inputs[i];
    }
}

// ===========================================================================
// LSTM step (r10 loop, jt-aware CTA mapping). Grid 1024 linear:
// jt = bid & 7, bx = bid >> 3  ->  co-resident CTAs (stride 148 = 4 mod 8)
// share 2 jt slices -> B L1-resident. CTA 256 thr = 8 warps (2 mw x 4 jw);
// warp tile M=32 x (4g x 8j). A tile 32KB via cp.async; B reg double-buffer.
// ===========================================================================
#define SMEM_TOTAL 32768

__global__ __launch_bounds__(256, 3) void lstm_step_kernel(int t) {
    extern __shared__ __align__(16) unsigned char smem[];
    const uint32_t sA = smem_to_u32(smem);
    const int tid  = threadIdx.x;
    const int lane = tid & 31, wid = tid >> 5;
    const int mw = wid >> 2;          // 0..1
    const int jw = wid & 3;           // 0..3
    const int bid = blockIdx.x;       // 0..1023
    const int jt = bid & 7;
    const int bx = bid >> 3;          // 0..127

    // ---- stage A tile (64 blocks = 4 batch-groups) into SMEM: 2048 uint4
    {
        const uint4* Asrc = &g_Afrag[t & 1][bx * 64][0];
#pragma unroll
        for (int i = 0; i < 8; i++)
            CP_ASYNC16(sA + tid * 16 + i * 4096,
                       (const char*)(Asrc + i * 256 + tid));
        CP_COMMIT();
    }

    // ---- prefetch chars while A streams
    const int gq = lane >> 2, t4 = lane & 3;
    int ch[2][2];
#pragma unroll
    for (int mt = 0; mt < 2; mt++)
#pragma unroll
        for (int rr = 0; rr < 2; rr++)
            ch[mt][rr] = g_inT[t * BATCH + bx * 64 + mw * 32 + mt * 16 + gq + rr * 8];

    // ---- prefetch B iter 0 (2 blocks: gate pairs)
    const uint4* __restrict__ Bp = &g_Bfrag[(jt * 4 + jw) * 32][lane];
    uint4 bv0 = Bp[0], bv1 = Bp[32];

    CP_WAIT0();
    __syncthreads();

    float acc[2][4][4];
#pragma unroll
    for (int mt = 0; mt < 2; mt++)
#pragma unroll
        for (int g = 0; g < 4; g++)
#pragma unroll
            for (int e = 0; e < 4; e++) acc[mt][g][e] = 0.0f;

    // A smem: block (mw*2+mt)*16 + it, 512B/block
    const uint32_t aoff0 = sA + (mw * 2 + 0) * 16 * 512 + lane * 16;
    const uint32_t aoff1 = sA + (mw * 2 + 1) * 16 * 512 + lane * 16;

#pragma unroll 4
    for (int it = 0; it < 16; it++) {
        uint4 bn0, bn1;
        if (it < 15) {
            const uint4* p = Bp + (it + 1) * 64;
            bn0 = p[0]; bn1 = p[32];
        } else {
            bn0 = bv0; bn1 = bv1;
        }

        uint32_t ah[2][4];
        {
            uint32_t o = it * 512;
            LDS128(ah[0][0], ah[0][1], ah[0][2], ah[0][3], aoff0 + o);
            LDS128(ah[1][0], ah[1][1], ah[1][2], ah[1][3], aoff1 + o);
        }

#pragma unroll
        for (int mt = 0; mt < 2; mt++) {
            MMA16816(acc[mt][0], ah[mt], bv0.x, bv0.y);
            MMA16816(acc[mt][1], ah[mt], bv0.z, bv0.w);
            MMA16816(acc[mt][2], ah[mt], bv1.x, bv1.y);
            MMA16816(acc[mt][3], ah[mt], bv1.z, bv1.w);
        }
        bv0 = bn0; bv1 = bn1;
    }

    // ---- Epilogue: z = acc + Wxb[char] -> gates -> c; h stored as A-frags.
    const int jcol = jt * 32 + jw * 8 + t4 * 2;   // even
    const int blk_base = jt * 2 + (jw >> 1);
    uint32_t* __restrict__ Aout = (uint32_t*)g_Afrag[(t + 1) & 1];

#pragma unroll
    for (int mt = 0; mt < 2; mt++) {
        const int grp = bx * 4 + mw * 2 + mt;
#pragma unroll
        for (int rr = 0; rr < 2; rr++) {
            const int b = bx * 64 + mw * 32 + mt * 16 + gq + rr * 8;
            const float* wrow = g_Wxb + (size_t)ch[mt][rr] * 1024;
            float2 wx2[4];
#pragma unroll
            for (int g = 0; g < 4; g++)
                wx2[g] = *(const float2*)&wrow[g * 256 + jcol];
            float2 c2 = *(const float2*)&g_c[(size_t)b * HID + jcol];

            float cn[2], hn[2];
#pragma unroll
            for (int e = 0; e < 2; e++) {
                float zi = acc[mt][0][rr * 2 + e] + (e ? wx2[0].y : wx2[0].x);
                float zf = acc[mt][1][rr * 2 + e] + (e ? wx2[1].y : wx2[1].x);
                float zg = acc[mt][2][rr * 2 + e] + (e ? wx2[2].y : wx2[2].x);
                float zo = acc[mt][3][rr * 2 + e] + (e ? wx2[3].y : wx2[3].x);
                float ig = sigf(zi), fg = sigf(zf);
                float gg = tanh_(zg), og = sigf(zo);
                float cold = e ? c2.y : c2.x;
                float cc = fg * cold + ig * gg;
                cn[e] = cc;
                hn[e] = og * tanh_(cc);
            }
            *(float2*)&g_c[(size_t)b * HID + jcol] = make_float2(cn[0], cn[1]);

            __half2 phi = __halves2half2(__float2half(hn[0]), __float2half(hn[1]));
            const int reg = rr + 2 * (jw & 1);
            uint32_t idx = (uint32_t)(((grp * 16 + blk_base) * 32 + lane) * 4 + reg);
            Aout[idx] = *(uint32_t*)&phi;

            if (t == SEQ - 1)
                *(float2*)&g_hfin[(size_t)b * HID + jcol] = make_float2(hn[0], hn[1]);
        }
    }
}

// ===========================================================================
// Dense + softmax (reads g_hfin, float)
// ===========================================================================
#define DROWS 8

__global__ __launch_bounds__(128) void dense_softmax_kernel(
    const float* __restrict__ Wd,   // [256, 128]
    const float* __restrict__ bd,   // [128]
    float*       __restrict__ out)  // [BATCH, 128]
{
    const int b0  = blockIdx.x * DROWS;
    const int tid = threadIdx.x;

    __shared__ float hs[DROWS][HID];
    __shared__ float ls[DROWS][VOCAB];

#pragma unroll
    for (int s = 0; s < DROWS * HID / 128; s++) {
        int e = tid + s * 128;
        hs[e >> 8][e & 255] = g_hfin[(size_t)b0 * HID + e];
    }
    __syncthreads();

    float acc[DROWS];
    float bv = bd[tid];
#pragma unroll
    for (int r = 0; r < DROWS; r++) acc[r] = bv;

#pragma unroll 8
    for (int k = 0; k < HID; k++) {
        float w = Wd[k * VOCAB + tid];
#pragma unroll
        for (int r = 0; r < DROWS; r++) acc[r] += hs[r][k] * w;
    }

#pragma unroll
    for (int r = 0; r < DROWS; r++) ls[r][tid] = acc[r];
    __syncthreads();

    const int w = tid >> 5, lane = tid & 31;
#pragma unroll
    for (int rr = 0; rr < 2; rr++) {
        int r = w * 2 + rr;
        float v[4];
        float m = -1e30f;
#pragma unroll
        for (int q = 0; q < 4; q++) {
            v[q] = ls[r][lane + q * 32];
            m = fmaxf(m, v[q]);
        }
#pragma unroll
        for (int o = 16; o > 0; o >>= 1) m = fmaxf(m, __shfl_xor_sync(0xffffffffu, m, o));
        float s = 0.0f;
#pragma unroll
        for (int q = 0; q < 4; q++) {
            v[q] = __expf(v[q] - m);
            s += v[q];
        }
#pragma unroll
        for (int o = 16; o > 0; o >>= 1) s += __shfl_xor_sync(0xffffffffu, s, o);
        float inv = 1.0f / s;
#pragma unroll
        for (int q = 0; q < 4; q++)
            out[(b0 + r) * VOCAB + lane + q * 32] = v[q] * inv;
    }
}

// ===========================================================================
extern "C" void kernel_launch(void* const* d_in, const int* in_sizes, int n_in,
                              void* d_out, int out_size) {
    const int*   inputs = (const int*)d_in[0];
    const float* Wx     = (const float*)d_in[1];
    const float* Wh     = (const float*)d_in[2];
    const float* b      = (const float*)d_in[3];
    const float* Wd     = (const float*)d_in[4];
    const float* bd     = (const float*)d_in[5];
    float*       out    = (float*)d_out;

    cudaFuncSetAttribute(lstm_step_kernel,
                         cudaFuncAttributeMaxDynamicSharedMemorySize, SMEM_TOTAL);

    prep_all_kernel<<<2048, 256>>>(inputs, Wh, Wx, b);

    for (int t = 0; t < SEQ; t++)
        lstm_step_kernel<<<1024, 256, SMEM_TOTAL>>>(t);

    dense_softmax_kernel<<<BATCH / DROWS, 128>>>(Wd, bd, out);
}